// round 2
// baseline (speedup 1.0000x reference)
#include <cuda_runtime.h>
#include <math.h>

#define B 512
#define S 512
#define WW 3
#define E 128
#define H 100
#define T 64

// Scratch (static device globals — no runtime allocation)
__device__ float g_em[(size_t)S * B * T];   // em[s][b][t]  (64 MB)
__device__ float g_mask[(size_t)S * B];     // mask[s][b] as 0/1 float
__device__ float g_num[B];                  // numerator per batch

// ---------------------------------------------------------------------------
// Kernel A: fused embedding gather + MLP (emb -> tanh(emb@W1+b1) -> @W2+b2)
// One block processes ROWS=64 consecutive (b,s) rows. Weights cached in smem.
// sW2 overlays sEmbT (sEmbT dead after phase 2; sW2 loaded at phase-2 end).
// ---------------------------------------------------------------------------
#define ROWS 64
#define ATHREADS 256

extern "C" __global__ void __launch_bounds__(ATHREADS)
mlp_kernel(const int* __restrict__ inputs,
           const float* __restrict__ emb_table,
           const float* __restrict__ W1, const float* __restrict__ b1,
           const float* __restrict__ W2, const float* __restrict__ b2)
{
    extern __shared__ float sm[];
    float* sW1   = sm;                    // E*H   = 12800 floats
    float* sEmbT = sW1 + E * H;           // E*ROWS= 8192   [e][r]
    float* sW2   = sEmbT;                 // H*T   = 6400 (overlays sEmbT, phase 3)
    float* sHT   = sEmbT + E * ROWS;      // H*ROWS= 6400   [j][r]
    float* sB1   = sHT + H * ROWS;        // 104
    float* sB2   = sB1 + 104;             // 64
    int*   sIdx  = (int*)(sB2 + 64);      // ROWS*3

    const int tid  = threadIdx.x;
    const int row0 = blockIdx.x * ROWS;
    const int b    = row0 >> 9;           // / S
    const int s0   = row0 & (S - 1);

    // --- load W1 / biases / indices into smem ---
    {
        const float4* W1v = (const float4*)W1;
        float4* sW1v = (float4*)sW1;
        for (int i = tid; i < (E * H) / 4; i += ATHREADS) sW1v[i] = W1v[i];
        if (tid < H) sB1[tid] = b1[tid];
        if (tid < T) sB2[tid] = b2[tid];
        for (int i = tid; i < ROWS * WW; i += ATHREADS)
            sIdx[i] = inputs[(size_t)row0 * WW + i];
    }
    __syncthreads();

    // --- phase 1: embedding gather-sum, stored transposed sEmbT[e][r] ---
    for (int v = tid; v < ROWS * E; v += ATHREADS) {
        int r = v >> 7;          // / E
        int e = v & (E - 1);
        float acc = 0.f;
#pragma unroll
        for (int w = 0; w < WW; w++) {
            int idx = sIdx[r * WW + w];
            acc += __ldg(&emb_table[(size_t)idx * E + e]);
        }
        sEmbT[e * ROWS + r] = acc;
    }
    if (tid < ROWS) {
        int r = tid;
        int nz = (sIdx[r * 3] != 0) + (sIdx[r * 3 + 1] != 0) + (sIdx[r * 3 + 2] != 0);
        g_mask[(size_t)(s0 + r) * B + b] = (nz != 0) ? 1.f : 0.f;
    }
    __syncthreads();

    // --- phase 2: h = tanh(emb @ W1 + b1), stored transposed sHT[j][r] ---
    // tiles of 4 rows x 4 j; 16 row-groups x 25 j-groups = 400 tiles
    for (int tile = tid; tile < 16 * 25; tile += ATHREADS) {
        int rg = tile & 15;
        int jg = tile >> 4;
        float acc[4][4];
#pragma unroll
        for (int a = 0; a < 4; a++)
#pragma unroll
            for (int c = 0; c < 4; c++) acc[a][c] = sB1[jg * 4 + c];
#pragma unroll 4
        for (int k = 0; k < E; k++) {
            float4 em4 = *(const float4*)&sEmbT[k * ROWS + rg * 4];
            float4 w4  = *(const float4*)&sW1[k * H + jg * 4];
            float ea[4] = {em4.x, em4.y, em4.z, em4.w};
            float wa[4] = {w4.x, w4.y, w4.z, w4.w};
#pragma unroll
            for (int a = 0; a < 4; a++)
#pragma unroll
                for (int c = 0; c < 4; c++) acc[a][c] += ea[a] * wa[c];
        }
#pragma unroll
        for (int a = 0; a < 4; a++)
#pragma unroll
            for (int c = 0; c < 4; c++)
                sHT[(jg * 4 + c) * ROWS + rg * 4 + a] = tanhf(acc[a][c]);
    }
    __syncthreads();   // phase-2 reads of sEmbT complete; safe to overlay with sW2

    // --- load W2 into (former sEmbT) space ---
    {
        const float4* W2v = (const float4*)W2;
        float4* sW2v = (float4*)sW2;
        for (int i = tid; i < (H * T) / 4; i += ATHREADS) sW2v[i] = W2v[i];
    }
    __syncthreads();

    // --- phase 3: em = h @ W2 + b2, write g_em[s][b][t] ---
    {
        int rg = tid & 15;      // row group
        int tg = tid >> 4;      // t group (0..15)
        float acc[4][4];
#pragma unroll
        for (int a = 0; a < 4; a++)
#pragma unroll
            for (int c = 0; c < 4; c++) acc[a][c] = sB2[tg * 4 + c];
#pragma unroll 4
        for (int k = 0; k < H; k++) {
            float4 h4 = *(const float4*)&sHT[k * ROWS + rg * 4];
            float4 w4 = *(const float4*)&sW2[k * T + tg * 4];
            float ha[4] = {h4.x, h4.y, h4.z, h4.w};
            float wa[4] = {w4.x, w4.y, w4.z, w4.w};
#pragma unroll
            for (int a = 0; a < 4; a++)
#pragma unroll
                for (int c = 0; c < 4; c++) acc[a][c] += ha[a] * wa[c];
        }
#pragma unroll
        for (int a = 0; a < 4; a++) {
            int s = s0 + rg * 4 + a;
            float4 o = make_float4(acc[a][0], acc[a][1], acc[a][2], acc[a][3]);
            *(float4*)&g_em[((size_t)s * B + b) * T + tg * 4] = o;
        }
    }
}

// ---------------------------------------------------------------------------
// Kernel B: numerator (gold-path score) — one warp per batch
// ---------------------------------------------------------------------------
extern "C" __global__ void __launch_bounds__(256)
num_kernel(const int* __restrict__ tags,
           const float* __restrict__ transitions,
           const float* __restrict__ start_trans,
           const float* __restrict__ end_trans)
{
    int warp = threadIdx.x >> 5;
    int lane = threadIdx.x & 31;
    int b = blockIdx.x * 8 + warp;
    const int* tb = tags + (size_t)b * S;

    float part = 0.f;
    int cnt = 0;
    for (int s = lane; s < S; s += 32) {
        float mk = g_mask[(size_t)s * B + b];
        cnt += (mk != 0.f);
        if (s >= 1) {
            int tp = tb[s - 1];
            int tc = tb[s];
            part += (transitions[tp * T + tc] + g_em[((size_t)s * B + b) * T + tc]) * mk;
        }
    }
#pragma unroll
    for (int o = 16; o; o >>= 1) {
        part += __shfl_xor_sync(0xffffffffu, part, o);
        cnt  += __shfl_xor_sync(0xffffffffu, cnt, o);
    }
    if (lane == 0) {
        int t0 = tb[0];
        float sc = start_trans[t0] + g_em[(size_t)b * T + t0] + part;
        int last = tb[cnt - 1];
        g_num[b] = sc + end_trans[last];
    }
}

// ---------------------------------------------------------------------------
// Kernel C: CRF forward scan.
//   lse_t(alpha[t] + trans[t,t']) = log( exp(alpha - m) @ exp(trans) ) + m
// Block: NB=4 batches, 256 threads. Thread (b_local, t') owns alpha[b][t'],
// keeps column Mexp[:, t'] in 64 registers.
// ---------------------------------------------------------------------------
#define NB 4
#define CTHREADS 256

extern "C" __global__ void __launch_bounds__(CTHREADS)
fwd_kernel(const float* __restrict__ transitions,
           const float* __restrict__ start_trans,
           const float* __restrict__ end_trans,
           float* __restrict__ out)
{
    __shared__ float sM[T * T];
    __shared__ float sE[T * NB];
    __shared__ float sRed[8];

    const int tid   = threadIdx.x;
    const int bl    = tid >> 6;       // 0..3
    const int tp    = tid & 63;       // t'
    const int warp  = tid >> 5;
    const int bglob = blockIdx.x * NB + bl;

    for (int i = tid; i < T * T; i += CTHREADS) sM[i] = expf(transitions[i]);
    __syncthreads();

    float Mreg[T];
#pragma unroll
    for (int t = 0; t < T; t++) Mreg[t] = sM[t * T + tp];

    float alpha = start_trans[tp] + g_em[(size_t)bglob * T + tp];  // s = 0
    __syncthreads();

    for (int s = 1; s < S; s++) {
        float emv = g_em[((size_t)s * B + bglob) * T + tp];
        float mk  = g_mask[(size_t)s * B + bglob];

        float m = alpha;
#pragma unroll
        for (int o = 16; o; o >>= 1)
            m = fmaxf(m, __shfl_xor_sync(0xffffffffu, m, o));
        if ((tid & 31) == 0) sRed[warp] = m;
        __syncthreads();
        m = fmaxf(sRed[bl * 2], sRed[bl * 2 + 1]);

        sE[tp * NB + bl] = expf(alpha - m);
        __syncthreads();

        float acc = 0.f;
#pragma unroll
        for (int t = 0; t < T; t++) acc += sE[t * NB + bl] * Mreg[t];

        float nxt = logf(acc) + m + emv;
        alpha = (mk != 0.f) ? nxt : alpha;
    }

    // denominator = lse_t(alpha + end_trans)
    float v = alpha + end_trans[tp];
    float m = v;
#pragma unroll
    for (int o = 16; o; o >>= 1)
        m = fmaxf(m, __shfl_xor_sync(0xffffffffu, m, o));
    if ((tid & 31) == 0) sRed[warp] = m;
    __syncthreads();
    m = fmaxf(sRed[bl * 2], sRed[bl * 2 + 1]);

    float e = expf(v - m);
#pragma unroll
    for (int o = 16; o; o >>= 1)
        e += __shfl_xor_sync(0xffffffffu, e, o);
    __syncthreads();   // sRed reads above complete before rewrite
    if ((tid & 31) == 0) sRed[warp] = e;
    __syncthreads();

    if (tp == 0) {
        float den = m + logf(sRed[bl * 2] + sRed[bl * 2 + 1]);
        out[bglob] = den - g_num[bglob];
    }
}

// ---------------------------------------------------------------------------
extern "C" void kernel_launch(void* const* d_in, const int* in_sizes, int n_in,
                              void* d_out, int out_size)
{
    const int*   inputs      = (const int*)  d_in[0];
    const int*   tags        = (const int*)  d_in[1];
    const float* emb_table   = (const float*)d_in[2];
    const float* W1          = (const float*)d_in[3];
    const float* b1          = (const float*)d_in[4];
    const float* W2          = (const float*)d_in[5];
    const float* b2          = (const float*)d_in[6];
    const float* start_trans = (const float*)d_in[7];
    const float* end_trans   = (const float*)d_in[8];
    const float* transitions = (const float*)d_in[9];
    float* out = (float*)d_out;

    const int smemA = (E * H + E * ROWS + H * ROWS + 104 + 64) * 4
                      + ROWS * WW * 4;
    cudaFuncSetAttribute(mlp_kernel,
                         cudaFuncAttributeMaxDynamicSharedMemorySize, smemA);

    mlp_kernel<<<(B * S) / ROWS, ATHREADS, smemA>>>(inputs, emb_table,
                                                    W1, b1, W2, b2);
    num_kernel<<<B / 8, 256>>>(tags, transitions, start_trans, end_trans);
    fwd_kernel<<<B / NB, CTHREADS>>>(transitions, start_trans, end_trans, out);
}

// round 3
// speedup vs baseline: 1.0122x; 1.0122x over previous
#include <cuda_runtime.h>
#include <math.h>

#define B 512
#define S 512
#define WW 3
#define E 128
#define H 100
#define T 64

// Scratch (static device globals — no runtime allocation)
__device__ float g_em[(size_t)S * B * T];   // em[s][b][t]  (64 MB)
__device__ float g_mask[(size_t)S * B];     // mask[s][b] as 0/1 float
__device__ float g_num[B];                  // numerator per batch

// ---- packed f32x2 helpers (sm_103a FFMA2 path, PTX-only) --------------------
typedef unsigned long long u64;

__device__ __forceinline__ u64 pack2(float lo, float hi) {
    u64 d;
    asm("mov.b64 %0, {%1, %2};" : "=l"(d) : "r"(__float_as_uint(lo)), "r"(__float_as_uint(hi)));
    return d;
}
__device__ __forceinline__ void unpack2(float& lo, float& hi, u64 v) {
    unsigned int a, b2;
    asm("mov.b64 {%0, %1}, %2;" : "=r"(a), "=r"(b2) : "l"(v));
    lo = __uint_as_float(a); hi = __uint_as_float(b2);
}
__device__ __forceinline__ void fma2(u64& d, u64 a, u64 b2, u64 c) {
    asm("fma.rn.f32x2 %0, %1, %2, %3;" : "=l"(d) : "l"(a), "l"(b2), "l"(c));
}

// ---------------------------------------------------------------------------
// Kernel A: fused embedding gather + MLP. One block = 64 (b,s) rows.
// GEMM phases use 8x8 register tiles with packed fma.rn.f32x2.
// sW2 overlays sEmbT (dead after GEMM1).
// ---------------------------------------------------------------------------
#define ROWS 64
#define ATHREADS 256
#define HPAD 104   // H padded to multiple of 8

extern "C" __global__ void __launch_bounds__(ATHREADS, 2)
mlp_kernel(const int* __restrict__ inputs,
           const float* __restrict__ emb_table,
           const float* __restrict__ W1, const float* __restrict__ b1,
           const float* __restrict__ W2, const float* __restrict__ b2)
{
    extern __shared__ float sm[];
    float* sW1   = sm;                    // E*H   = 12800 floats
    float* sEmbT = sW1 + E * H;           // E*ROWS= 8192   [e][r]
    float* sW2   = sEmbT;                 // H*T   = 6400 (overlay, phase 3)
    float* sHT   = sEmbT + E * ROWS;      // HPAD*ROWS = 6656  [j][r]
    float* sB1   = sHT + HPAD * ROWS;     // 104
    float* sB2   = sB1 + HPAD;            // 64
    int*   sIdx  = (int*)(sB2 + T);       // ROWS*3

    const int tid  = threadIdx.x;
    const int row0 = blockIdx.x * ROWS;
    const int b    = row0 >> 9;           // / S
    const int s0   = row0 & (S - 1);

    // --- load W1 / biases / indices ---
    {
        const float4* W1v = (const float4*)W1;
        float4* sW1v = (float4*)sW1;
        for (int i = tid; i < (E * H) / 4; i += ATHREADS) sW1v[i] = W1v[i];
        if (tid < H) sB1[tid] = b1[tid];
        else if (tid < HPAD) sB1[tid] = 0.f;
        if (tid >= 128 && tid < 128 + T) sB2[tid - 128] = b2[tid - 128];
        for (int i = tid; i < ROWS * WW; i += ATHREADS)
            sIdx[i] = inputs[(size_t)row0 * WW + i];
    }
    __syncthreads();

    // --- phase 1: embedding gather-sum (float4), store transposed [e][r] ---
    for (int i = tid; i < (ROWS * E) / 4; i += ATHREADS) {
        int r  = i & 63;
        int e4 = i >> 6;
        float4 acc = make_float4(0.f, 0.f, 0.f, 0.f);
#pragma unroll
        for (int w = 0; w < WW; w++) {
            int idx = sIdx[r * WW + w];
            float4 v = __ldg((const float4*)&emb_table[(size_t)idx * E + e4 * 4]);
            acc.x += v.x; acc.y += v.y; acc.z += v.z; acc.w += v.w;
        }
        sEmbT[(e4 * 4 + 0) * ROWS + r] = acc.x;
        sEmbT[(e4 * 4 + 1) * ROWS + r] = acc.y;
        sEmbT[(e4 * 4 + 2) * ROWS + r] = acc.z;
        sEmbT[(e4 * 4 + 3) * ROWS + r] = acc.w;
    }
    if (tid < ROWS) {
        int r = tid;
        int nz = (sIdx[r * 3] != 0) + (sIdx[r * 3 + 1] != 0) + (sIdx[r * 3 + 2] != 0);
        g_mask[(size_t)(s0 + r) * B + b] = (nz != 0) ? 1.f : 0.f;
    }
    __syncthreads();

    // --- phase 2: h = tanh(emb @ W1 + b1) -> sHT[j][r], 8x8 tiles, FFMA2 ---
    // 8 row-groups x 13 col-groups = 104 tiles (cols padded to 104; j>=100 junk
    // lands in sHT pad rows, never read by GEMM2).
    if (tid < 104) {
        const int rg = tid & 7;        // *8 rows
        const int cg = tid >> 3;       // *8 cols (0..12)
        u64 acc[4][8];
#pragma unroll
        for (int c = 0; c < 8; c++) {
            float bb = sB1[cg * 8 + c];
            u64 p = pack2(bb, bb);
#pragma unroll
            for (int a = 0; a < 4; a++) acc[a][c] = p;
        }
#pragma unroll 4
        for (int k = 0; k < E; k++) {
            const u64* rowp = (const u64*)&sEmbT[k * ROWS + rg * 8];
            u64 ra[4];
#pragma unroll
            for (int a = 0; a < 4; a++) ra[a] = rowp[a];
            float4 wA = *(const float4*)&sW1[k * H + cg * 8];
            float4 wB = *(const float4*)&sW1[k * H + cg * 8 + 4];
            u64 wp[8];
            wp[0] = pack2(wA.x, wA.x); wp[1] = pack2(wA.y, wA.y);
            wp[2] = pack2(wA.z, wA.z); wp[3] = pack2(wA.w, wA.w);
            wp[4] = pack2(wB.x, wB.x); wp[5] = pack2(wB.y, wB.y);
            wp[6] = pack2(wB.z, wB.z); wp[7] = pack2(wB.w, wB.w);
#pragma unroll
            for (int a = 0; a < 4; a++)
#pragma unroll
                for (int c = 0; c < 8; c++) fma2(acc[a][c], ra[a], wp[c], acc[a][c]);
        }
#pragma unroll
        for (int a = 0; a < 4; a++)
#pragma unroll
            for (int c = 0; c < 8; c++) {
                float lo, hi; unpack2(lo, hi, acc[a][c]);
                float2 o = make_float2(tanhf(lo), tanhf(hi));
                *(float2*)&sHT[(cg * 8 + c) * ROWS + rg * 8 + a * 2] = o;
            }
    }
    __syncthreads();   // GEMM1 reads of sEmbT/sW1 done -> overlay with W2

    {
        const float4* W2v = (const float4*)W2;
        float4* sW2v = (float4*)sW2;
        for (int i = tid; i < (H * T) / 4; i += ATHREADS) sW2v[i] = W2v[i];
    }
    __syncthreads();

    // --- phase 3: em = h @ W2 + b2 -> g_em[s][b][t], 8x8 tiles, FFMA2 ---
    if (tid < 64) {
        const int rg = tid & 7;        // *8 rows (s)
        const int tg = tid >> 3;       // *8 cols (t)
        u64 acc[4][8];
#pragma unroll
        for (int c = 0; c < 8; c++) {
            float bb = sB2[tg * 8 + c];
            u64 p = pack2(bb, bb);
#pragma unroll
            for (int a = 0; a < 4; a++) acc[a][c] = p;
        }
#pragma unroll 4
        for (int k = 0; k < H; k++) {
            const u64* rowp = (const u64*)&sHT[k * ROWS + rg * 8];
            u64 ra[4];
#pragma unroll
            for (int a = 0; a < 4; a++) ra[a] = rowp[a];
            float4 wA = *(const float4*)&sW2[k * T + tg * 8];
            float4 wB = *(const float4*)&sW2[k * T + tg * 8 + 4];
            u64 wp[8];
            wp[0] = pack2(wA.x, wA.x); wp[1] = pack2(wA.y, wA.y);
            wp[2] = pack2(wA.z, wA.z); wp[3] = pack2(wA.w, wA.w);
            wp[4] = pack2(wB.x, wB.x); wp[5] = pack2(wB.y, wB.y);
            wp[6] = pack2(wB.z, wB.z); wp[7] = pack2(wB.w, wB.w);
#pragma unroll
            for (int a = 0; a < 4; a++)
#pragma unroll
                for (int c = 0; c < 8; c++) fma2(acc[a][c], ra[a], wp[c], acc[a][c]);
        }
#pragma unroll
        for (int a = 0; a < 4; a++) {
            float r0v[8], r1v[8];
#pragma unroll
            for (int c = 0; c < 8; c++) unpack2(r0v[c], r1v[c], acc[a][c]);
            int sA = s0 + rg * 8 + a * 2;
            float* dst0 = &g_em[((size_t)sA * B + b) * T + tg * 8];
            float* dst1 = &g_em[((size_t)(sA + 1) * B + b) * T + tg * 8];
            *(float4*)dst0       = make_float4(r0v[0], r0v[1], r0v[2], r0v[3]);
            *(float4*)(dst0 + 4) = make_float4(r0v[4], r0v[5], r0v[6], r0v[7]);
            *(float4*)dst1       = make_float4(r1v[0], r1v[1], r1v[2], r1v[3]);
            *(float4*)(dst1 + 4) = make_float4(r1v[4], r1v[5], r1v[6], r1v[7]);
        }
    }
}

// ---------------------------------------------------------------------------
// Kernel B: numerator — one warp per batch
// ---------------------------------------------------------------------------
extern "C" __global__ void __launch_bounds__(256)
num_kernel(const int* __restrict__ tags,
           const float* __restrict__ transitions,
           const float* __restrict__ start_trans,
           const float* __restrict__ end_trans)
{
    int warp = threadIdx.x >> 5;
    int lane = threadIdx.x & 31;
    int b = blockIdx.x * 8 + warp;
    const int* tb = tags + (size_t)b * S;

    float part = 0.f;
    int cnt = 0;
    for (int s = lane; s < S; s += 32) {
        float mk = g_mask[(size_t)s * B + b];
        cnt += (mk != 0.f);
        if (s >= 1) {
            int tp = tb[s - 1];
            int tc = tb[s];
            part += (transitions[tp * T + tc] + g_em[((size_t)s * B + b) * T + tc]) * mk;
        }
    }
#pragma unroll
    for (int o = 16; o; o >>= 1) {
        part += __shfl_xor_sync(0xffffffffu, part, o);
        cnt  += __shfl_xor_sync(0xffffffffu, cnt, o);
    }
    if (lane == 0) {
        int t0 = tb[0];
        float sc = start_trans[t0] + g_em[(size_t)b * T + t0] + part;
        int last = tb[cnt - 1];
        g_num[b] = sc + end_trans[last];
    }
}

// ---------------------------------------------------------------------------
// Kernel C: CRF forward scan, warp-per-batch, barrier-free linear domain.
//   beta' = (beta @ exp(trans)) * exp(em);  renormalize by warp-max every
//   4 steps, carrying log-offset C.  Lane l owns states 2l, 2l+1.
// ---------------------------------------------------------------------------
#define FB 4          // batches (warps) per block
#define CTHREADS (FB * 32)

extern "C" __global__ void __launch_bounds__(CTHREADS)
fwd_kernel(const float* __restrict__ transitions,
           const float* __restrict__ start_trans,
           const float* __restrict__ end_trans,
           float* __restrict__ out)
{
    __shared__ float2 sMp[T * 32];    // [t][l] = (Mexp[t][2l], Mexp[t][2l+1])

    const int tid  = threadIdx.x;
    const int w    = tid >> 5;
    const int l    = tid & 31;
    const int b    = blockIdx.x * FB + w;

    for (int i = tid; i < T * T; i += CTHREADS) {
        int t  = i >> 6;
        int tp = i & 63;
        ((float*)sMp)[(t * 32 + (tp >> 1)) * 2 + (tp & 1)] = expf(transitions[i]);
    }
    __syncthreads();

    float2 st2 = *(const float2*)&start_trans[2 * l];
    float2 em0 = *(const float2*)&g_em[(size_t)b * T + 2 * l];
    float b0 = expf(st2.x + em0.x);
    float b1 = expf(st2.y + em0.y);
    float C = 0.f;

    float2 emn = *(const float2*)&g_em[((size_t)1 * B + b) * T + 2 * l];
    float  mkn = g_mask[(size_t)1 * B + b];

    for (int s = 1; s < S; s++) {
        float2 emc = emn;
        float  mk  = mkn;
        int sn = (s + 1 < S) ? s + 1 : S - 1;           // prefetch next step
        emn = *(const float2*)&g_em[((size_t)sn * B + b) * T + 2 * l];
        mkn = g_mask[(size_t)sn * B + b];

        float acc0 = 0.f, acc1 = 0.f;
#pragma unroll
        for (int t = 0; t < T; t++) {
            float bb = __shfl_sync(0xffffffffu, (t & 1) ? b1 : b0, t >> 1);
            float2 m2 = sMp[t * 32 + l];
            acc0 = fmaf(bb, m2.x, acc0);
            acc1 = fmaf(bb, m2.y, acc1);
        }
        float n0 = acc0 * expf(emc.x);
        float n1 = acc1 * expf(emc.y);
        if (mk != 0.f) { b0 = n0; b1 = n1; }

        if ((s & 3) == 0) {                              // periodic renorm
            float mx = fmaxf(b0, b1);
#pragma unroll
            for (int o = 16; o; o >>= 1)
                mx = fmaxf(mx, __shfl_xor_sync(0xffffffffu, mx, o));
            float inv = 1.0f / mx;
            C += logf(mx);
            b0 *= inv; b1 *= inv;
        }
    }

    // denominator = C + log(sum_t beta_t * exp(end_trans_t))
    float2 ed = *(const float2*)&end_trans[2 * l];
    float sum = b0 * expf(ed.x) + b1 * expf(ed.y);
#pragma unroll
    for (int o = 16; o; o >>= 1)
        sum += __shfl_xor_sync(0xffffffffu, sum, o);
    if (l == 0)
        out[b] = C + logf(sum) - g_num[b];
}

// ---------------------------------------------------------------------------
extern "C" void kernel_launch(void* const* d_in, const int* in_sizes, int n_in,
                              void* d_out, int out_size)
{
    const int*   inputs      = (const int*)  d_in[0];
    const int*   tags        = (const int*)  d_in[1];
    const float* emb_table   = (const float*)d_in[2];
    const float* W1          = (const float*)d_in[3];
    const float* b1          = (const float*)d_in[4];
    const float* W2          = (const float*)d_in[5];
    const float* b2          = (const float*)d_in[6];
    const float* start_trans = (const float*)d_in[7];
    const float* end_trans   = (const float*)d_in[8];
    const float* transitions = (const float*)d_in[9];
    float* out = (float*)d_out;

    const int smemA = (E * H + E * ROWS + HPAD * ROWS + HPAD + T) * 4
                      + ROWS * WW * 4;
    cudaFuncSetAttribute(mlp_kernel,
                         cudaFuncAttributeMaxDynamicSharedMemorySize, smemA);

    mlp_kernel<<<(B * S) / ROWS, ATHREADS, smemA>>>(inputs, emb_table,
                                                    W1, b1, W2, b2);
    num_kernel<<<B / 8, 256>>>(tags, transitions, start_trans, end_trans);
    fwd_kernel<<<B / FB, CTHREADS>>>(transitions, start_trans, end_trans, out);
}

// round 5
// speedup vs baseline: 1.1041x; 1.0908x over previous
#include <cuda_runtime.h>
#include <math.h>

#define B 512
#define S 512
#define WW 3
#define E 128
#define H 100
#define T 64

// Scratch (static device globals — no runtime allocation)
__device__ float g_em[(size_t)S * B * T];   // em[s][b][t]
__device__ float g_mask[(size_t)S * B];
__device__ float g_num[B];

typedef unsigned long long u64;

__device__ __forceinline__ u64 pack2(float lo, float hi) {
    u64 d; asm("mov.b64 %0, {%1, %2};" : "=l"(d) : "f"(lo), "f"(hi)); return d;
}
__device__ __forceinline__ void unpack2(float& lo, float& hi, u64 v) {
    asm("mov.b64 {%0, %1}, %2;" : "=f"(lo), "=f"(hi) : "l"(v));
}
__device__ __forceinline__ u64 fma2(u64 a, u64 b2, u64 c) {
    u64 d; asm("fma.rn.f32x2 %0, %1, %2, %3;" : "=l"(d) : "l"(a), "l"(b2), "l"(c));
    return d;
}
__device__ __forceinline__ float ex2f(float x) {
    float r; asm("ex2.approx.f32 %0, %1;" : "=f"(r) : "f"(x)); return r;
}
__device__ __forceinline__ float exp_f(float x) { return ex2f(x * 1.4426950408889634f); }
__device__ __forceinline__ float log_f(float x) {
    float r; asm("lg2.approx.f32 %0, %1;" : "=f"(r) : "f"(x));
    return r * 0.6931471805599453f;
}
__device__ __forceinline__ float tanh_f(float x) {
    float e = ex2f(x * 2.8853900817779268f);      // e^(2x)
    float r; asm("rcp.approx.f32 %0, %1;" : "=f"(r) : "f"(e + 1.0f));
    return fmaf(-2.0f, r, 1.0f);
}

// ---------------------------------------------------------------------------
// Kernel A: fused gather + MLP. One block = 128 (b,s) rows (same b).
// k-pair FFMA2: acc u64 = (sum over even k, sum over odd k); horizontal add
// at the end. Weights packed into u64 k-pairs in smem; activations are
// natural contiguous pairs. No operand replication.
// smem byte layout (total 226,976):
//   A  [0      ..  53,248): sW1p  u64[64 kp][104 j]
//   Bm [53,248 .. 135,168): sEmb  64 kp x (16 groups x 80B)  (8 rows/group)
//   C  [135,168.. 199,168): raw W1 stage (51,200) -> h pairs 50 kp2 x 1280B
//   D  [199,168.. 224,768): sW2p  u64[50 kp][64 t]
//   sB1 104f, sB2 64f, sIdx 384i
// ---------------------------------------------------------------------------
#define ROWS 128
#define ATHREADS 256
#define KP1 64
#define JP 104
#define KP2 50

#define OFF_A   0
#define OFF_B   53248
#define OFF_C   135168
#define OFF_D   199168
#define OFF_SB1 224768
#define OFF_SB2 225184
#define OFF_IDX 225440
#define SMEM_TOTAL 226976

extern "C" __global__ void __launch_bounds__(ATHREADS, 1)
mlp_kernel(const int* __restrict__ inputs,
           const float* __restrict__ emb_table,
           const float* __restrict__ W1, const float* __restrict__ b1,
           const float* __restrict__ W2, const float* __restrict__ b2)
{
    extern __shared__ char smem[];
    u64*   sW1p  = (u64*)(smem + OFF_A);
    char*  sEmbB = smem + OFF_B;
    char*  sCB   = smem + OFF_C;
    u64*   sW2p  = (u64*)(smem + OFF_D);
    float* sB1   = (float*)(smem + OFF_SB1);
    float* sB2   = (float*)(smem + OFF_SB2);
    int*   sIdx  = (int*)(smem + OFF_IDX);

    const int tid  = threadIdx.x;
    const int row0 = blockIdx.x * ROWS;
    const int b    = row0 >> 9;
    const int s0   = row0 & (S - 1);

    // --- stage raw W1 -> C; biases; indices ---
    {
        float4* dst = (float4*)sCB;
        const float4* src = (const float4*)W1;
        for (int i = tid; i < (E * H) / 4; i += ATHREADS) dst[i] = src[i];
        if (tid < JP) sB1[tid] = (tid < H) ? b1[tid] : 0.f;
        if (tid >= 128 && tid < 128 + T) sB2[tid - 128] = b2[tid - 128];
        for (int i = tid; i < ROWS * WW; i += ATHREADS)
            sIdx[i] = inputs[(size_t)row0 * WW + i];
    }
    __syncthreads();

    // --- pack W1 -> A; embedding gather -> B (independent, same phase) ---
    {
        const float* raw = (const float*)sCB;
        for (int i = tid; i < KP1 * JP; i += ATHREADS) {
            int kp = i / JP, j = i - kp * JP;
            sW1p[i] = (j < H) ? pack2(raw[(2 * kp) * H + j], raw[(2 * kp + 1) * H + j])
                              : 0ull;
        }
        for (int i = tid; i < (ROWS * E) / 8; i += ATHREADS) {
            int r  = i & (ROWS - 1);
            int e8 = i >> 7;                 // 0..15, covers k = e8*8..e8*8+7
            float4 a0 = make_float4(0.f, 0.f, 0.f, 0.f);
            float4 a1 = make_float4(0.f, 0.f, 0.f, 0.f);
#pragma unroll
            for (int w = 0; w < WW; w++) {
                int idx = sIdx[r * WW + w];
                const float4* p = (const float4*)&emb_table[(size_t)idx * E + e8 * 8];
                float4 v0 = __ldg(p), v1 = __ldg(p + 1);
                a0.x += v0.x; a0.y += v0.y; a0.z += v0.z; a0.w += v0.w;
                a1.x += v1.x; a1.y += v1.y; a1.z += v1.z; a1.w += v1.w;
            }
            int g = r >> 3, ri = r & 7;
            char* base = sEmbB + (size_t)(e8 * 4) * 1280 + g * 80 + ri * 8;
            *(u64*)(base)        = pack2(a0.x, a0.y);
            *(u64*)(base + 1280) = pack2(a0.z, a0.w);
            *(u64*)(base + 2560) = pack2(a1.x, a1.y);
            *(u64*)(base + 3840) = pack2(a1.z, a1.w);
        }
        if (tid < ROWS) {
            int nz = (sIdx[tid * 3] != 0) + (sIdx[tid * 3 + 1] != 0) + (sIdx[tid * 3 + 2] != 0);
            g_mask[(size_t)(s0 + tid) * B + b] = nz ? 1.f : 0.f;
        }
    }
    __syncthreads();

    // --- GEMM1: 208 threads, 8x8 tile; tanh; store h pairs -> C ---
    if (tid < 208) {
        const int rg = tid & 15;             // row group (8 rows)
        const int cg = tid >> 4;             // 0..12
        const int j0 = cg * 8;
        u64 acc[8][8];
#pragma unroll
        for (int jj = 0; jj < 8; jj++) {
            u64 bz = pack2(sB1[j0 + jj], 0.f);
#pragma unroll
            for (int a = 0; a < 8; a++) acc[a][jj] = bz;
        }
        const char* ebase = sEmbB + rg * 80;
        const u64*  wbase = sW1p + j0;
#pragma unroll 2
        for (int kp = 0; kp < KP1; kp++) {
            u64 e[8], w[8];
            const u64* ep = (const u64*)(ebase + (size_t)kp * 1280);
            const u64* wp = wbase + kp * JP;
#pragma unroll
            for (int a = 0; a < 8; a++) e[a] = ep[a];
#pragma unroll
            for (int jj = 0; jj < 8; jj++) w[jj] = wp[jj];
#pragma unroll
            for (int a = 0; a < 8; a++)
#pragma unroll
                for (int jj = 0; jj < 8; jj++)
                    acc[a][jj] = fma2(e[a], w[jj], acc[a][jj]);
        }
#pragma unroll
        for (int jj2 = 0; jj2 < 4; jj2++) {
            int kp2 = (j0 >> 1) + jj2;
            if (kp2 < KP2) {
                char* hb = sCB + (size_t)kp2 * 1280 + rg * 80;
#pragma unroll
                for (int a = 0; a < 8; a++) {
                    float x0, y0, x1, y1;
                    unpack2(x0, y0, acc[a][jj2 * 2]);
                    unpack2(x1, y1, acc[a][jj2 * 2 + 1]);
                    *(u64*)(hb + a * 8) = pack2(tanh_f(x0 + y0), tanh_f(x1 + y1));
                }
            }
        }
    }
    __syncthreads();

    // --- stage raw W2 into B region (sEmb dead) ---
    {
        float4* dst = (float4*)sEmbB;
        const float4* src = (const float4*)W2;
        for (int i = tid; i < (H * T) / 4; i += ATHREADS) dst[i] = src[i];
    }
    __syncthreads();
    // --- pack W2 -> D ---
    {
        const float* raw = (const float*)sEmbB;
        for (int i = tid; i < KP2 * T; i += ATHREADS) {
            int kp = i >> 6, t = i & 63;
            sW2p[i] = pack2(raw[(2 * kp) * T + t], raw[(2 * kp + 1) * T + t]);
        }
    }
    __syncthreads();

    // --- GEMM2: 128 threads, 8x8 tile; store em -> g_em ---
    if (tid < 128) {
        const int rg = tid & 15;
        const int tg = tid >> 4;             // 0..7
        const int t0 = tg * 8;
        u64 acc[8][8];
#pragma unroll
        for (int tt = 0; tt < 8; tt++) {
            u64 bz = pack2(sB2[t0 + tt], 0.f);
#pragma unroll
            for (int a = 0; a < 8; a++) acc[a][tt] = bz;
        }
        const char* hbase = sCB + rg * 80;
        const u64*  wbase = sW2p + t0;
#pragma unroll 2
        for (int kp = 0; kp < KP2; kp++) {
            u64 e[8], w[8];
            const u64* ep = (const u64*)(hbase + (size_t)kp * 1280);
            const u64* wp = wbase + kp * T;
#pragma unroll
            for (int a = 0; a < 8; a++) e[a] = ep[a];
#pragma unroll
            for (int tt = 0; tt < 8; tt++) w[tt] = wp[tt];
#pragma unroll
            for (int a = 0; a < 8; a++)
#pragma unroll
                for (int tt = 0; tt < 8; tt++)
                    acc[a][tt] = fma2(e[a], w[tt], acc[a][tt]);
        }
#pragma unroll
        for (int a = 0; a < 8; a++) {
            float o[8];
#pragma unroll
            for (int tt = 0; tt < 8; tt++) {
                float lo, hi; unpack2(lo, hi, acc[a][tt]);
                o[tt] = lo + hi;
            }
            int s = s0 + rg * 8 + a;
            float* dst = &g_em[((size_t)s * B + b) * T + t0];
            *(float4*)dst       = make_float4(o[0], o[1], o[2], o[3]);
            *(float4*)(dst + 4) = make_float4(o[4], o[5], o[6], o[7]);
        }
    }
}

// ---------------------------------------------------------------------------
// Kernel B: numerator — one warp per batch
// ---------------------------------------------------------------------------
extern "C" __global__ void __launch_bounds__(256)
num_kernel(const int* __restrict__ tags,
           const float* __restrict__ transitions,
           const float* __restrict__ start_trans,
           const float* __restrict__ end_trans)
{
    int warp = threadIdx.x >> 5;
    int lane = threadIdx.x & 31;
    int b = blockIdx.x * 8 + warp;
    const int* tb = tags + (size_t)b * S;

    float part = 0.f;
    int cnt = 0;
    for (int s = lane; s < S; s += 32) {
        float mk = g_mask[(size_t)s * B + b];
        cnt += (mk != 0.f);
        if (s >= 1) {
            int tp = tb[s - 1];
            int tc = tb[s];
            part += (transitions[tp * T + tc] + g_em[((size_t)s * B + b) * T + tc]) * mk;
        }
    }
#pragma unroll
    for (int o = 16; o; o >>= 1) {
        part += __shfl_xor_sync(0xffffffffu, part, o);
        cnt  += __shfl_xor_sync(0xffffffffu, cnt, o);
    }
    if (lane == 0) {
        int t0 = tb[0];
        float sc = start_trans[t0] + g_em[(size_t)b * T + t0] + part;
        int last = tb[cnt - 1];
        g_num[b] = sc + end_trans[last];
    }
}

// ---------------------------------------------------------------------------
// Kernel C: CRF forward scan. Warp per batch; exp(transitions) columns
// register-resident (64 u64 / thread); beta broadcast via 64-bit shfl;
// FFMA2 pairs over source states; renorm every 4 steps.
// ---------------------------------------------------------------------------
#define FB 4
#define CTHREADS (FB * 32)

extern "C" __global__ void __launch_bounds__(CTHREADS, 1)
fwd_kernel(const float* __restrict__ transitions,
           const float* __restrict__ start_trans,
           const float* __restrict__ end_trans,
           float* __restrict__ out)
{
    const int tid = threadIdx.x;
    const int l   = tid & 31;
    const int b   = blockIdx.x * FB + (tid >> 5);

    // Mp[p][c] = (exp(trans[2p][2l+c]), exp(trans[2p+1][2l+c]))
    u64 Mp[32][2];
#pragma unroll
    for (int p = 0; p < 32; p++)
#pragma unroll
        for (int c = 0; c < 2; c++) {
            float lo = exp_f(__ldg(&transitions[(2 * p) * T + 2 * l + c]));
            float hi = exp_f(__ldg(&transitions[(2 * p + 1) * T + 2 * l + c]));
            Mp[p][c] = pack2(lo, hi);
        }

    float2 em0 = *(const float2*)&g_em[(size_t)b * T + 2 * l];
    float b0 = exp_f(__ldg(&start_trans[2 * l])     + em0.x);
    float b1 = exp_f(__ldg(&start_trans[2 * l + 1]) + em0.y);
    float C = 0.f;

    float2 emA = *(const float2*)&g_em[((size_t)1 * B + b) * T + 2 * l];
    float  mkA = g_mask[(size_t)1 * B + b];
    float2 emB = *(const float2*)&g_em[((size_t)2 * B + b) * T + 2 * l];
    float  mkB = g_mask[(size_t)2 * B + b];

    for (int s = 1; s < S; s++) {
        float2 emc = emA; float mk = mkA;
        emA = emB; mkA = mkB;
        int sn = (s + 2 < S) ? s + 2 : S - 1;
        emB = *(const float2*)&g_em[((size_t)sn * B + b) * T + 2 * l];
        mkB = g_mask[(size_t)sn * B + b];

        u64 bp = pack2(b0, b1);
        u64 a00 = 0ull, a01 = 0ull, a10 = 0ull, a11 = 0ull;
#pragma unroll
        for (int p = 0; p < 32; p++) {
            u64 bb = __shfl_sync(0xffffffffu, bp, p);
            if (p & 1) { a01 = fma2(bb, Mp[p][0], a01); a11 = fma2(bb, Mp[p][1], a11); }
            else       { a00 = fma2(bb, Mp[p][0], a00); a10 = fma2(bb, Mp[p][1], a10); }
        }
        float x0, y0, x1, y1, x2, y2, x3, y3;
        unpack2(x0, y0, a00); unpack2(x1, y1, a01);
        unpack2(x2, y2, a10); unpack2(x3, y3, a11);
        float n0 = ((x0 + y0) + (x1 + y1)) * exp_f(emc.x);
        float n1 = ((x2 + y2) + (x3 + y3)) * exp_f(emc.y);
        if (mk != 0.f) { b0 = n0; b1 = n1; }

        if ((s & 3) == 0) {
            float mx = fmaxf(b0, b1);
#pragma unroll
            for (int o = 16; o; o >>= 1)
                mx = fmaxf(mx, __shfl_xor_sync(0xffffffffu, mx, o));
            C += log_f(mx);
            float inv = 1.0f / mx;
            b0 *= inv; b1 *= inv;
        }
    }

    float sum = b0 * exp_f(__ldg(&end_trans[2 * l]))
              + b1 * exp_f(__ldg(&end_trans[2 * l + 1]));
#pragma unroll
    for (int o = 16; o; o >>= 1)
        sum += __shfl_xor_sync(0xffffffffu, sum, o);
    if (l == 0)
        out[b] = C + log_f(sum) - g_num[b];
}

// ---------------------------------------------------------------------------
extern "C" void kernel_launch(void* const* d_in, const int* in_sizes, int n_in,
                              void* d_out, int out_size)
{
    const int*   inputs      = (const int*)  d_in[0];
    const int*   tags        = (const int*)  d_in[1];
    const float* emb_table   = (const float*)d_in[2];
    const float* W1          = (const float*)d_in[3];
    const float* b1          = (const float*)d_in[4];
    const float* W2          = (const float*)d_in[5];
    const float* b2          = (const float*)d_in[6];
    const float* start_trans = (const float*)d_in[7];
    const float* end_trans   = (const float*)d_in[8];
    const float* transitions = (const float*)d_in[9];
    float* out = (float*)d_out;

    cudaFuncSetAttribute(mlp_kernel,
                         cudaFuncAttributeMaxDynamicSharedMemorySize, SMEM_TOTAL);

    mlp_kernel<<<(B * S) / ROWS, ATHREADS, SMEM_TOTAL>>>(inputs, emb_table,
                                                         W1, b1, W2, b2);
    num_kernel<<<B / 8, 256>>>(tags, transitions, start_trans, end_trans);
    fwd_kernel<<<B / FB, CTHREADS>>>(transitions, start_trans, end_trans, out);
}

// round 7
// speedup vs baseline: 1.3655x; 1.2367x over previous
#include <cuda_runtime.h>
#include <math.h>
#include <stdint.h>

#define B 512
#define S 512
#define WW 3
#define E 128
#define H 100
#define T 64

// Scratch (static device globals — no runtime allocation)
__device__ float g_em[(size_t)S * B * T];   // em[s][b][t]
__device__ float g_mask[(size_t)S * B];
__device__ float g_num[B];

typedef unsigned long long u64;

#define KP1 64      // k-pairs for GEMM1 (E/2)
#define JP  104     // H padded to 8
#define KP2 50      // k-pairs for GEMM2 (H/2)

__device__ __align__(16) u64 gW1p[KP1 * JP];   // (W1[2kp][j], W1[2kp+1][j])
__device__ __align__(16) u64 gW2p[KP2 * T];    // (W2[2kp][t], W2[2kp+1][t])

// ---- helpers ---------------------------------------------------------------
__device__ __forceinline__ u64 pack2(float lo, float hi) {
    u64 d; asm("mov.b64 %0, {%1, %2};" : "=l"(d) : "f"(lo), "f"(hi)); return d;
}
__device__ __forceinline__ void unpack2(float& lo, float& hi, u64 v) {
    asm("mov.b64 {%0, %1}, %2;" : "=f"(lo), "=f"(hi) : "l"(v));
}
__device__ __forceinline__ u64 fma2(u64 a, u64 b2, u64 c) {
    u64 d; asm("fma.rn.f32x2 %0, %1, %2, %3;" : "=l"(d) : "l"(a), "l"(b2), "l"(c));
    return d;
}
__device__ __forceinline__ float ex2f(float x) {
    float r; asm("ex2.approx.f32 %0, %1;" : "=f"(r) : "f"(x)); return r;
}
__device__ __forceinline__ float exp_f(float x) { return ex2f(x * 1.4426950408889634f); }
__device__ __forceinline__ float log_f(float x) {
    float r; asm("lg2.approx.f32 %0, %1;" : "=f"(r) : "f"(x));
    return r * 0.6931471805599453f;
}
__device__ __forceinline__ float tanh_f(float x) {
    float e = ex2f(x * 2.8853900817779268f);
    float r; asm("rcp.approx.f32 %0, %1;" : "=f"(r) : "f"(e + 1.0f));
    return fmaf(-2.0f, r, 1.0f);
}

// ---------------------------------------------------------------------------
// prep: pack weights into k-pair u64 buffers (runs once per launch, ~3us)
// ---------------------------------------------------------------------------
extern "C" __global__ void __launch_bounds__(256)
prep_kernel(const float* __restrict__ W1, const float* __restrict__ W2)
{
    int i = blockIdx.x * 256 + threadIdx.x;
    if (i < KP1 * JP) {
        int kp = i / JP, j = i - kp * JP;
        float lo = (j < H) ? W1[(2 * kp) * H + j]     : 0.f;
        float hi = (j < H) ? W1[(2 * kp + 1) * H + j] : 0.f;
        gW1p[i] = pack2(lo, hi);
    } else {
        int i2 = i - KP1 * JP;
        if (i2 < KP2 * T) {
            int kp = i2 >> 6, t = i2 & 63;
            gW2p[i2] = pack2(W2[(2 * kp) * T + t], W2[(2 * kp + 1) * T + t]);
        }
    }
}

// ---------------------------------------------------------------------------
// Kernel A: fused gather + MLP. One block = 64 rows. Activations in smem
// (k-pair u64, 8-row groups with 80B stride); weights streamed from L2.
// smem:
//   EMB [0      .. 40,960): 64 kp x (8 grp x 80B)
//   Hs  [40,960 .. 72,960): 50 kp x (8 grp x 80B)
//   sB1 [72,960): 104f   sB2 [73,376): 64f   sIdx [73,632): 192i
// ---------------------------------------------------------------------------
#define ROWS 64
#define MTHREADS 256
#define OFF_EMB 0
#define OFF_H   40960
#define OFF_SB1 72960
#define OFF_SB2 73376
#define OFF_IDX 73632
#define SMEM_SZ 74400

extern "C" __global__ void __launch_bounds__(MTHREADS, 2)
mlp_kernel(const int* __restrict__ inputs,
           const float* __restrict__ emb_table,
           const float* __restrict__ b1, const float* __restrict__ b2)
{
    extern __shared__ char smem[];
    float* sB1  = (float*)(smem + OFF_SB1);
    float* sB2  = (float*)(smem + OFF_SB2);
    int*   sIdx = (int*)(smem + OFF_IDX);

    const int tid  = threadIdx.x;
    const int row0 = blockIdx.x * ROWS;
    const int b    = row0 >> 9;
    const int s0   = row0 & (S - 1);

    // biases + indices
    if (tid < JP) sB1[tid] = (tid < H) ? b1[tid] : 0.f;
    if (tid >= 128 && tid < 128 + T) sB2[tid - 128] = b2[tid - 128];
    if (tid < ROWS * WW) sIdx[tid] = inputs[(size_t)row0 * WW + tid];
    __syncthreads();

    // gather-sum -> sEmb (k-pair u64)
    for (int i = tid; i < (ROWS * E) / 8; i += MTHREADS) {   // 1024
        int r  = i & (ROWS - 1);
        int e8 = i >> 6;                                     // 0..15
        float a0 = 0.f, a1 = 0.f, a2 = 0.f, a3 = 0.f;
        float a4 = 0.f, a5 = 0.f, a6 = 0.f, a7 = 0.f;
#pragma unroll
        for (int w = 0; w < WW; w++) {
            int idx = sIdx[r * WW + w];
            const float4* p = (const float4*)&emb_table[(size_t)idx * E + e8 * 8];
            float4 v0 = __ldg(p), v1 = __ldg(p + 1);
            a0 += v0.x; a1 += v0.y; a2 += v0.z; a3 += v0.w;
            a4 += v1.x; a5 += v1.y; a6 += v1.z; a7 += v1.w;
        }
        char* base = smem + OFF_EMB + (size_t)(e8 * 4) * 640 + (r >> 3) * 80 + (r & 7) * 8;
        *(u64*)(base)        = pack2(a0, a1);
        *(u64*)(base + 640)  = pack2(a2, a3);
        *(u64*)(base + 1280) = pack2(a4, a5);
        *(u64*)(base + 1920) = pack2(a6, a7);
    }
    if (tid < ROWS) {
        int nz = (sIdx[tid * 3] != 0) + (sIdx[tid * 3 + 1] != 0) + (sIdx[tid * 3 + 2] != 0);
        g_mask[(size_t)(s0 + tid) * B + b] = nz ? 1.f : 0.f;
    }
    __syncthreads();

    // GEMM1: 208 threads, 4 rows x 8 j; weights streamed from gW1p (L2)
    if (tid < 208) {
        const int rg = tid & 15;
        const int cg = tid >> 4;             // 0..12
        const int j0 = cg * 8;
        u64 acc[4][8];
#pragma unroll
        for (int jj = 0; jj < 8; jj++) {
            u64 bz = pack2(sB1[j0 + jj], 0.f);
#pragma unroll
            for (int a = 0; a < 4; a++) acc[a][jj] = bz;
        }
        const char* ebase = smem + OFF_EMB + (rg >> 1) * 80 + (rg & 1) * 32;
        const u64*  wbase = gW1p + j0;
#pragma unroll 2
        for (int kp = 0; kp < KP1; kp++) {
            u64 e[4];
            const u64* ep = (const u64*)(ebase + (size_t)kp * 640);
#pragma unroll
            for (int a = 0; a < 4; a++) e[a] = ep[a];
            uint4 wv[4];
            const uint4* wp = (const uint4*)(wbase + kp * JP);
#pragma unroll
            for (int q = 0; q < 4; q++) wv[q] = __ldg(wp + q);
            const u64* w = (const u64*)wv;
#pragma unroll
            for (int a = 0; a < 4; a++)
#pragma unroll
                for (int jj = 0; jj < 8; jj++)
                    acc[a][jj] = fma2(e[a], w[jj], acc[a][jj]);
        }
        // tanh + store h as j-pair u64 into Hs
#pragma unroll
        for (int jp = 0; jp < 4; jp++) {
            int kp2 = (j0 >> 1) + jp;
            if (kp2 < KP2) {
                char* hb = smem + OFF_H + (size_t)kp2 * 640 + (rg >> 1) * 80 + (rg & 1) * 32;
#pragma unroll
                for (int a = 0; a < 4; a++) {
                    float x0, y0, x1, y1;
                    unpack2(x0, y0, acc[a][jp * 2]);
                    unpack2(x1, y1, acc[a][jp * 2 + 1]);
                    *(u64*)(hb + a * 8) = pack2(tanh_f(x0 + y0), tanh_f(x1 + y1));
                }
            }
        }
    }
    __syncthreads();

    // GEMM2: 256 threads, 2 rows x 8 t; weights from gW2p (L2)
    {
        const int rg = tid & 31;             // 2-row groups
        const int tg = tid >> 5;             // 0..7
        const int t0 = tg * 8;
        u64 acc[2][8];
#pragma unroll
        for (int tt = 0; tt < 8; tt++) {
            u64 bz = pack2(sB2[t0 + tt], 0.f);
#pragma unroll
            for (int a = 0; a < 2; a++) acc[a][tt] = bz;
        }
        const char* hbase = smem + OFF_H + (rg >> 2) * 80 + (rg & 3) * 16;
        const u64*  wbase = gW2p + t0;
#pragma unroll 2
        for (int kp = 0; kp < KP2; kp++) {
            u64 e[2];
            const u64* ep = (const u64*)(hbase + (size_t)kp * 640);
            e[0] = ep[0]; e[1] = ep[1];
            uint4 wv[4];
            const uint4* wp = (const uint4*)(wbase + kp * T);
#pragma unroll
            for (int q = 0; q < 4; q++) wv[q] = __ldg(wp + q);
            const u64* w = (const u64*)wv;
#pragma unroll
            for (int a = 0; a < 2; a++)
#pragma unroll
                for (int tt = 0; tt < 8; tt++)
                    acc[a][tt] = fma2(e[a], w[tt], acc[a][tt]);
        }
#pragma unroll
        for (int a = 0; a < 2; a++) {
            float o[8];
#pragma unroll
            for (int tt = 0; tt < 8; tt++) {
                float lo, hi; unpack2(lo, hi, acc[a][tt]);
                o[tt] = lo + hi;
            }
            int s = s0 + rg * 2 + a;
            float* dst = &g_em[((size_t)s * B + b) * T + t0];
            *(float4*)dst       = make_float4(o[0], o[1], o[2], o[3]);
            *(float4*)(dst + 4) = make_float4(o[4], o[5], o[6], o[7]);
        }
    }
}

// ---------------------------------------------------------------------------
// Kernel B: numerator — one warp per batch
// ---------------------------------------------------------------------------
extern "C" __global__ void __launch_bounds__(256)
num_kernel(const int* __restrict__ tags,
           const float* __restrict__ transitions,
           const float* __restrict__ start_trans,
           const float* __restrict__ end_trans)
{
    int warp = threadIdx.x >> 5;
    int lane = threadIdx.x & 31;
    int b = blockIdx.x * 8 + warp;
    const int* tb = tags + (size_t)b * S;

    float part = 0.f;
    int cnt = 0;
    for (int s = lane; s < S; s += 32) {
        float mk = g_mask[(size_t)s * B + b];
        cnt += (mk != 0.f);
        if (s >= 1) {
            int tp = tb[s - 1];
            int tc = tb[s];
            part += (transitions[tp * T + tc] + g_em[((size_t)s * B + b) * T + tc]) * mk;
        }
    }
#pragma unroll
    for (int o = 16; o; o >>= 1) {
        part += __shfl_xor_sync(0xffffffffu, part, o);
        cnt  += __shfl_xor_sync(0xffffffffu, cnt, o);
    }
    if (lane == 0) {
        int t0 = tb[0];
        float sc = start_trans[t0] + g_em[(size_t)b * T + t0] + part;
        int last = tb[cnt - 1];
        g_num[b] = sc + end_trans[last];
    }
}

// ---------------------------------------------------------------------------
// Kernel C: CRF forward scan. Warp per batch; Mexp register-resident;
// 64-bit shfl broadcast; FFMA2; renorm every 4 steps; prefetch depth 4.
// ---------------------------------------------------------------------------
#define FB 4
#define CTHREADS (FB * 32)

extern "C" __global__ void __launch_bounds__(CTHREADS, 1)
fwd_kernel(const float* __restrict__ transitions,
           const float* __restrict__ start_trans,
           const float* __restrict__ end_trans,
           float* __restrict__ out)
{
    const int tid = threadIdx.x;
    const int l   = tid & 31;
    const int b   = blockIdx.x * FB + (tid >> 5);

    u64 Mp[32][2];
#pragma unroll
    for (int p = 0; p < 32; p++)
#pragma unroll
        for (int c = 0; c < 2; c++) {
            float lo = exp_f(__ldg(&transitions[(2 * p) * T + 2 * l + c]));
            float hi = exp_f(__ldg(&transitions[(2 * p + 1) * T + 2 * l + c]));
            Mp[p][c] = pack2(lo, hi);
        }

    float2 em0 = *(const float2*)&g_em[(size_t)b * T + 2 * l];
    float b0 = exp_f(__ldg(&start_trans[2 * l])     + em0.x);
    float b1 = exp_f(__ldg(&start_trans[2 * l + 1]) + em0.y);
    float C = 0.f;

    float2 emr[4];
    float  mkr[4];
#pragma unroll
    for (int j = 0; j < 4; j++) {
        int ss = 1 + j; if (ss > S - 1) ss = S - 1;
        emr[j] = *(const float2*)&g_em[((size_t)ss * B + b) * T + 2 * l];
        mkr[j] = g_mask[(size_t)ss * B + b];
    }

#pragma unroll 4
    for (int s = 1; s < S; s++) {
        int j = (s - 1) & 3;
        float2 emc = emr[j];
        float  mk  = mkr[j];
        int sn = s + 4; if (sn > S - 1) sn = S - 1;
        emr[j] = *(const float2*)&g_em[((size_t)sn * B + b) * T + 2 * l];
        mkr[j] = g_mask[(size_t)sn * B + b];

        u64 bp = pack2(b0, b1);
        u64 a00 = 0ull, a01 = 0ull, a10 = 0ull, a11 = 0ull;
#pragma unroll
        for (int p = 0; p < 32; p++) {
            u64 bb = __shfl_sync(0xffffffffu, bp, p);
            if (p & 1) { a01 = fma2(bb, Mp[p][0], a01); a11 = fma2(bb, Mp[p][1], a11); }
            else       { a00 = fma2(bb, Mp[p][0], a00); a10 = fma2(bb, Mp[p][1], a10); }
        }
        float x0, y0, x1, y1, x2, y2, x3, y3;
        unpack2(x0, y0, a00); unpack2(x1, y1, a01);
        unpack2(x2, y2, a10); unpack2(x3, y3, a11);
        float n0 = ((x0 + y0) + (x1 + y1)) * exp_f(emc.x);
        float n1 = ((x2 + y2) + (x3 + y3)) * exp_f(emc.y);
        if (mk != 0.f) { b0 = n0; b1 = n1; }

        if ((s & 3) == 0) {
            float mx = fmaxf(b0, b1);
#pragma unroll
            for (int o = 16; o; o >>= 1)
                mx = fmaxf(mx, __shfl_xor_sync(0xffffffffu, mx, o));
            C += log_f(mx);
            float inv = 1.0f / mx;
            b0 *= inv; b1 *= inv;
        }
    }

    float sum = b0 * exp_f(__ldg(&end_trans[2 * l]))
              + b1 * exp_f(__ldg(&end_trans[2 * l + 1]));
#pragma unroll
    for (int o = 16; o; o >>= 1)
        sum += __shfl_xor_sync(0xffffffffu, sum, o);
    if (l == 0)
        out[b] = C + log_f(sum) - g_num[b];
}

// ---------------------------------------------------------------------------
extern "C" void kernel_launch(void* const* d_in, const int* in_sizes, int n_in,
                              void* d_out, int out_size)
{
    const int*   inputs      = (const int*)  d_in[0];
    const int*   tags        = (const int*)  d_in[1];
    const float* emb_table   = (const float*)d_in[2];
    const float* W1          = (const float*)d_in[3];
    const float* b1          = (const float*)d_in[4];
    const float* W2          = (const float*)d_in[5];
    const float* b2          = (const float*)d_in[6];
    const float* start_trans = (const float*)d_in[7];
    const float* end_trans   = (const float*)d_in[8];
    const float* transitions = (const float*)d_in[9];
    float* out = (float*)d_out;

    cudaFuncSetAttribute(mlp_kernel,
                         cudaFuncAttributeMaxDynamicSharedMemorySize, SMEM_SZ);

    prep_kernel<<<(KP1 * JP + KP2 * T + 255) / 256, 256>>>(W1, W2);
    mlp_kernel<<<(B * S) / ROWS, MTHREADS, SMEM_SZ>>>(inputs, emb_table, b1, b2);
    num_kernel<<<B / 8, 256>>>(tags, transitions, start_trans, end_trans);
    fwd_kernel<<<B / FB, CTHREADS>>>(transitions, start_trans, end_trans, out);
}